// round 1
// baseline (speedup 1.0000x reference)
#include <cuda_runtime.h>

#define NCHUNKS 16
#define WARPS   8
#define ROWS    32
#define THREADS 256
#define MAX_ATOMS   16384
#define MAX_CLAUSES 4096

// Packed per-atom metadata: {A' , B' , fid(bits), clause_id(bits)}
// arg = A'*x[fid] + B'  with  e = exp2(arg) = exp(-z),  sigmoid(z) = 1/(1+e)
__device__ float4 g_meta[MAX_ATOMS];
__device__ float  g_gl[MAX_CLAUSES];          // gate[c]*leaf[c]
__device__ int    g_chunk_start[NCHUNKS + 1]; // clause-aligned atom ranges

__global__ void cln_setup(const float* __restrict__ w,
                          const float* __restrict__ eta,
                          const float* __restrict__ leaf,
                          const float* __restrict__ gate,
                          const int* __restrict__ fid,
                          const int* __restrict__ csgn,
                          const int* __restrict__ cids,
                          int n_atoms, int n_clauses, int cpc) {
    int i = blockIdx.x * blockDim.x + threadIdx.x;
    const float L2E = 1.4426950408889634f;   // log2(e)
    if (i < n_atoms) {
        float sB = (csgn[i] == 0) ? -100.0f : 100.0f;   // sign * B_CONST
        float A2 = -sB * w[i] * L2E;
        float B2 = -sB * (0.01f - eta[i]) * L2E;        // EPS = 0.01
        g_meta[i] = make_float4(A2, B2, __int_as_float(fid[i]), __int_as_float(cids[i]));
    }
    if (i < n_clauses) g_gl[i] = gate[i] * leaf[i];
    if (i <= NCHUNKS) {
        // lower_bound(cids, i*cpc) over sorted clause_ids
        int target = i * cpc, lo = 0, hi = n_atoms;
        while (lo < hi) {
            int mid = (lo + hi) >> 1;
            if (cids[mid] < target) lo = mid + 1; else hi = mid;
        }
        g_chunk_start[i] = lo;
    }
}

__global__ __launch_bounds__(THREADS)
void cln_main(const float* __restrict__ x, float* __restrict__ y,
              int nfeat, int cpc) {
    extern __shared__ float xs[];            // ROWS * (nfeat+1) floats, padded
    __shared__ float ys[ROWS];

    const int rowBase = blockIdx.x * ROWS;
    const int pad = nfeat + 1;

    // Stage 32 rows of x into shared (coalesced float4 loads)
    const int n4 = nfeat >> 2;
    for (int i = threadIdx.x; i < ROWS * n4; i += THREADS) {
        int row = i / n4, f4 = i - row * n4;
        float4 v = reinterpret_cast<const float4*>(
                       x + (size_t)(rowBase + row) * nfeat)[f4];
        float* d = xs + row * pad + (f4 << 2);
        d[0] = v.x; d[1] = v.y; d[2] = v.z; d[3] = v.w;
    }
    if (threadIdx.x < ROWS) ys[threadIdx.x] = 0.f;
    __syncthreads();

    const int warp = threadIdx.x >> 5;
    const int lane = threadIdx.x & 31;
    const int chunk = blockIdx.y * WARPS + warp;   // 0..NCHUNKS-1

    int a    = g_chunk_start[chunk];
    int aEnd = g_chunk_start[chunk + 1];
    int cur  = chunk * cpc;
    const int c1 = cur + cpc;

    const float* xrow = xs + lane * pad;  // lane == row-within-tile; stride 257 -> conflict-free
    float yacc = 0.f;
    float prod = 1.f;                     // prod of (1 + e_a) over atoms of current clause

    #pragma unroll 2
    for (; a < aEnd; ++a) {
        float4 m = g_meta[a];             // broadcast LDG.128, L1-resident
        int cid = __float_as_int(m.w);
        if (cid != cur) {
            yacc += __fdividef(g_gl[cur], prod);   // clause = 1/prod
            prod = 1.f;
            for (int c = cur + 1; c < cid; ++c) yacc += g_gl[c];  // empty clauses -> clause==1
            cur = cid;
        }
        float xv = xrow[__float_as_int(m.z)];
        float e  = exp2f(fmaf(m.x, xv, m.y));      // e = exp(-z), 1 MUFU
        prod = fminf(fmaf(prod, e, prod), 1e38f);  // clamp: no inf -> no inf*0 NaN
    }
    yacc += __fdividef(g_gl[cur], prod);
    for (int c = cur + 1; c < c1; ++c) yacc += g_gl[c];

    atomicAdd(&ys[lane], yacc);
    __syncthreads();
    if (threadIdx.x < ROWS)
        atomicAdd(&y[rowBase + threadIdx.x], ys[threadIdx.x]);
}

extern "C" void kernel_launch(void* const* d_in, const int* in_sizes, int n_in,
                              void* d_out, int out_size) {
    const float* x    = (const float*)d_in[0];
    const float* w    = (const float*)d_in[1];
    const float* eta  = (const float*)d_in[2];
    const float* leaf = (const float*)d_in[3];
    const float* gate = (const float*)d_in[4];
    const int*   fid  = (const int*)d_in[5];
    const int*   csgn = (const int*)d_in[6];
    const int*   cids = (const int*)d_in[7];

    const int n_atoms   = in_sizes[1];
    const int n_clauses = in_sizes[3];
    const int batch     = out_size;
    const int nfeat     = in_sizes[0] / batch;
    const int cpc       = n_clauses / NCHUNKS;

    cudaMemsetAsync(d_out, 0, (size_t)batch * sizeof(float));

    int setup_n = n_atoms;
    if (n_clauses > setup_n)  setup_n = n_clauses;
    if (NCHUNKS + 1 > setup_n) setup_n = NCHUNKS + 1;
    cln_setup<<<(setup_n + 255) / 256, 256>>>(w, eta, leaf, gate, fid, csgn, cids,
                                              n_atoms, n_clauses, cpc);

    dim3 grid(batch / ROWS, NCHUNKS / WARPS);
    size_t smem = (size_t)ROWS * (nfeat + 1) * sizeof(float);
    cln_main<<<grid, THREADS, smem>>>(x, (float*)d_out, nfeat, cpc);
}

// round 2
// speedup vs baseline: 1.0836x; 1.0836x over previous
#include <cuda_runtime.h>

#define NCHUNKS 16
#define WARPS   8
#define ROWS    64
#define THREADS 256
#define XPAD    257               // row stride in smem floats (conflict-free)
#define MAX_ATOMS   16384
#define MAX_CLAUSES 4096

// Packed per-atom metadata: {A' , B' , fid(bits), clause_id(bits)}
// arg = A'*x[fid] + B' ;  e = exp2(arg) = exp(-z) ;  sigmoid(z) = 1/(1+e)
__device__ float4 g_meta[MAX_ATOMS];
__device__ float  g_gl[MAX_CLAUSES];          // gate[c]*leaf[c]
__device__ int    g_chunk_start[NCHUNKS + 1]; // clause-aligned atom ranges

__global__ void cln_setup(const float* __restrict__ w,
                          const float* __restrict__ eta,
                          const float* __restrict__ leaf,
                          const float* __restrict__ gate,
                          const int* __restrict__ fid,
                          const int* __restrict__ csgn,
                          const int* __restrict__ cids,
                          int n_atoms, int n_clauses, int cpc) {
    int i = blockIdx.x * blockDim.x + threadIdx.x;
    const float L2E = 1.4426950408889634f;   // log2(e)
    if (i < n_atoms) {
        float sB = (csgn[i] == 0) ? -100.0f : 100.0f;   // sign * B_CONST
        float A2 = -sB * w[i] * L2E;
        float B2 = -sB * (0.01f - eta[i]) * L2E;        // EPS = 0.01
        g_meta[i] = make_float4(A2, B2, __int_as_float(fid[i]), __int_as_float(cids[i]));
    }
    if (i < n_clauses) g_gl[i] = gate[i] * leaf[i];
    if (i <= NCHUNKS) {
        int target = i * cpc, lo = 0, hi = n_atoms;
        while (lo < hi) {
            int mid = (lo + hi) >> 1;
            if (cids[mid] < target) lo = mid + 1; else hi = mid;
        }
        g_chunk_start[i] = lo;
    }
}

__global__ __launch_bounds__(THREADS)
void cln_main(const float* __restrict__ x, float* __restrict__ y,
              int nfeat, int cpc) {
    extern __shared__ float xs[];            // ROWS * XPAD floats
    __shared__ float ys[ROWS];

    const int rowBase = blockIdx.x * ROWS;

    // Stage 64 rows of x into shared (coalesced float4 loads, conflict-free stores)
    const int n4 = nfeat >> 2;
    for (int i = threadIdx.x; i < ROWS * n4; i += THREADS) {
        int row = i / n4, f4 = i - row * n4;
        float4 v = reinterpret_cast<const float4*>(
                       x + (size_t)(rowBase + row) * nfeat)[f4];
        float* d = xs + row * XPAD + (f4 << 2);
        d[0] = v.x; d[1] = v.y; d[2] = v.z; d[3] = v.w;
    }
    if (threadIdx.x < ROWS) ys[threadIdx.x] = 0.f;
    __syncthreads();

    const int warp = threadIdx.x >> 5;
    const int lane = threadIdx.x & 31;
    const int chunk = blockIdx.y * WARPS + warp;   // 0..NCHUNKS-1

    const int aEnd = g_chunk_start[chunk + 1];
    int cur  = chunk * cpc;
    const int c1 = cur + cpc;

    // lane owns rows (lane) and (lane+32): both LDS sets conflict-free,
    // second row reachable with an immediate offset from the first.
    const float* xr0 = xs + lane * XPAD;
    float y0 = 0.f, y1 = 0.f;
    float p0 = 1.f, p1 = 1.f;               // prod of (1 + e_a) per clause

    const float4* mp = g_meta + g_chunk_start[chunk];
    const float4* mpEnd = g_meta + aEnd;

    #pragma unroll 2
    for (; mp < mpEnd; ++mp) {
        float4 m = *mp;                      // broadcast LDG.128
        int cid = __float_as_int(m.w);
        if (cid != cur) {
            float g = g_gl[cur];
            y0 += __fdividef(g, p0);         // clause value = 1/prod
            y1 += __fdividef(g, p1);
            p0 = 1.f; p1 = 1.f;
            for (int c = cur + 1; c < cid; ++c) {   // empty clauses -> value 1
                float g2 = g_gl[c];
                y0 += g2; y1 += g2;
            }
            cur = cid;
        }
        int f = __float_as_int(m.z);
        float xv0 = xr0[f];
        float xv1 = xr0[f + 32 * XPAD];
        float e0 = exp2f(fmaf(m.x, xv0, m.y));
        float e1 = exp2f(fmaf(m.x, xv1, m.y));
        p0 = fminf(fmaf(p0, e0, p0), 1e38f); // clamp: no inf -> no inf*0 NaN
        p1 = fminf(fmaf(p1, e1, p1), 1e38f);
    }
    {
        float g = g_gl[cur];
        y0 += __fdividef(g, p0);
        y1 += __fdividef(g, p1);
        for (int c = cur + 1; c < c1; ++c) {
            float g2 = g_gl[c];
            y0 += g2; y1 += g2;
        }
    }

    atomicAdd(&ys[lane], y0);
    atomicAdd(&ys[lane + 32], y1);
    __syncthreads();
    if (threadIdx.x < ROWS)
        atomicAdd(&y[rowBase + threadIdx.x], ys[threadIdx.x]);
}

extern "C" void kernel_launch(void* const* d_in, const int* in_sizes, int n_in,
                              void* d_out, int out_size) {
    const float* x    = (const float*)d_in[0];
    const float* w    = (const float*)d_in[1];
    const float* eta  = (const float*)d_in[2];
    const float* leaf = (const float*)d_in[3];
    const float* gate = (const float*)d_in[4];
    const int*   fid  = (const int*)d_in[5];
    const int*   csgn = (const int*)d_in[6];
    const int*   cids = (const int*)d_in[7];

    const int n_atoms   = in_sizes[1];
    const int n_clauses = in_sizes[3];
    const int batch     = out_size;
    const int nfeat     = in_sizes[0] / batch;
    const int cpc       = n_clauses / NCHUNKS;

    cudaMemsetAsync(d_out, 0, (size_t)batch * sizeof(float));

    int setup_n = n_atoms;
    if (n_clauses > setup_n)   setup_n = n_clauses;
    if (NCHUNKS + 1 > setup_n) setup_n = NCHUNKS + 1;
    cln_setup<<<(setup_n + 255) / 256, 256>>>(w, eta, leaf, gate, fid, csgn, cids,
                                              n_atoms, n_clauses, cpc);

    size_t smem = (size_t)ROWS * XPAD * sizeof(float);
    cudaFuncSetAttribute(cln_main, cudaFuncAttributeMaxDynamicSharedMemorySize,
                         (int)smem);
    dim3 grid(batch / ROWS, NCHUNKS / WARPS);
    cln_main<<<grid, THREADS, smem>>>(x, (float*)d_out, nfeat, cpc);
}